// round 17
// baseline (speedup 1.0000x reference)
#include <cuda_runtime.h>
#include <cuda_bf16.h>
#include <mma.h>
#include <math.h>
#include <stdint.h>

using namespace nvcuda;

#define NN 50000
#define NE 1600000
#define DD 256
#define HH 8
#define HDIM 32
#define EDIM 32
#define D4 (4*DD)
#define DQKV 1024           // q | k | v | qe

// ---------------- scratch (device globals; no runtime allocation) ----------
__device__ float    g_qkv[(size_t)NN*DQKV];    // q | k | v | qe per row
__device__ float    g_scores[(size_t)NE*HH];
__device__ unsigned g_smax[(size_t)NN*HH];
__device__ float    g_ssum[(size_t)NN*HH];
__device__ float    g_agg[(size_t)NN*DD];
__device__ float    g_x1 [(size_t)NN*DD];
__device__ float    g_bqkv[DQKV];
// bf16 hi/lo operand arrays
__device__ __nv_bfloat16 g_xnh[(size_t)NN*DD];
__device__ __nv_bfloat16 g_xnl[(size_t)NN*DD];
__device__ __nv_bfloat16 g_aggh[(size_t)NN*DD];
__device__ __nv_bfloat16 g_aggl[(size_t)NN*DD];
__device__ __nv_bfloat16 g_hh[(size_t)NN*D4];
__device__ __nv_bfloat16 g_hl[(size_t)NN*D4];
// weights packed (element offsets):
// rows 0-1023 = qkv B: Wq(0) Wk(65536) Wv(131072) Wqe(196608)
// then Wo, W1, W2
#define WQO  0
#define WKO  65536
#define WVO  131072
#define WQEO 196608
#define WOO  262144
#define W1O  327680
#define W2O  589824
#define WTOT 851968
__device__ __nv_bfloat16 g_wh[WTOT];
__device__ __nv_bfloat16 g_wl[WTOT];

// ---------------- small helpers -------------------------------------------
__device__ __forceinline__ unsigned fenc(float f) {
    unsigned u = __float_as_uint(f);
    return (u & 0x80000000u) ? ~u : (u | 0x80000000u);
}
__device__ __forceinline__ float fdec(unsigned u) {
    return (u & 0x80000000u) ? __uint_as_float(u & 0x7fffffffu)
                             : __uint_as_float(~u);
}
__device__ __forceinline__ uint32_t pack_bf2(__nv_bfloat16 a, __nv_bfloat16 b) {
    return (uint32_t)__bfloat16_as_ushort(a) | ((uint32_t)__bfloat16_as_ushort(b) << 16);
}
__device__ __forceinline__ void cvt_hilo(float4 v, uint2& hi, uint2& lo) {
    __nv_bfloat16 hx = __float2bfloat16(v.x);
    __nv_bfloat16 hy = __float2bfloat16(v.y);
    __nv_bfloat16 hz = __float2bfloat16(v.z);
    __nv_bfloat16 hw = __float2bfloat16(v.w);
    __nv_bfloat16 lx = __float2bfloat16(v.x - __bfloat162float(hx));
    __nv_bfloat16 ly = __float2bfloat16(v.y - __bfloat162float(hy));
    __nv_bfloat16 lz = __float2bfloat16(v.z - __bfloat162float(hz));
    __nv_bfloat16 lw = __float2bfloat16(v.w - __bfloat162float(hw));
    hi.x = pack_bf2(hx, hy); hi.y = pack_bf2(hz, hw);
    lo.x = pack_bf2(lx, ly); lo.y = pack_bf2(lz, lw);
}
__device__ __forceinline__ float gelu_exact(float x) {
    return 0.5f * x * (1.0f + erff(x * 0.70710678118654752f));
}
__device__ __forceinline__ uint32_t smem_u32(const void* p) {
    uint32_t a;
    asm("{ .reg .u64 t; cvta.to.shared.u64 t, %1; cvt.u32.u64 %0, t; }"
        : "=r"(a) : "l"(p));
    return a;
}
__device__ __forceinline__ void cpa16(uint32_t dst, const void* src, bool p) {
    int sz = p ? 16 : 0;
    asm volatile("cp.async.cg.shared.global [%0], [%1], 16, %2;"
                 :: "r"(dst), "l"(src), "r"(sz));
}
__device__ __forceinline__ void red4(float* p, float a, float b, float c, float d) {
    asm volatile("red.global.add.v4.f32 [%0], {%1, %2, %3, %4};"
                 :: "l"(p), "f"(a), "f"(b), "f"(c), "f"(d) : "memory");
}
__device__ __forceinline__ void red1(float* p, float a) {
    asm volatile("red.global.add.f32 [%0], %1;" :: "l"(p), "f"(a) : "memory");
}
__device__ __forceinline__ float dot4(float4 a, float4 b) {
    return a.x*b.x + a.y*b.y + a.z*b.z + a.w*b.w;
}

// ============== bf16 hi/lo GEMM: C = act(A[M,K] @ B[N,K]^T + bias) =========
// MODE 0: C fp32; MODE 1: C = res + scale*(val+bias); MODE 2: GELU -> bf16 hi/lo
#define LDT 40
#define TILE_B (128*LDT*2)          // 10240 B
#define STAGE_B (4*TILE_B)          // 40960 B (Ahi,Alo,Bhi,Blo)
#define GEMM_SMEM (2*STAGE_B)       // 81920 B (also covers 128x132 fp32 epilogue)

__device__ __forceinline__ void stage_load(
    char* smem, int buf,
    const __nv_bfloat16* __restrict__ Ahi, const __nv_bfloat16* __restrict__ Alo,
    const __nv_bfloat16* __restrict__ Bhi, const __nv_bfloat16* __restrict__ Blo,
    int bm, int bn, int M, int K, int kc, int tid)
{
    uint32_t sb = smem_u32(smem) + buf * STAGE_B;
    #pragma unroll
    for (int j = 0; j < 2; j++) {
        int idx = tid + j*256;               // 0..511 chunks of 16B
        int row = idx >> 2;                  // 0..127
        int c   = (idx & 3) * 8;             // bf16 column
        uint32_t soff = (uint32_t)(row*LDT + c) * 2;
        size_t gA = (size_t)(bm + row) * K + kc*32 + c;
        size_t gB = (size_t)(bn + row) * K + kc*32 + c;
        bool pa = (bm + row) < M;
        cpa16(sb + soff,              pa ? (const void*)(Ahi + gA) : (const void*)Ahi, pa);
        cpa16(sb + TILE_B + soff,     pa ? (const void*)(Alo + gA) : (const void*)Alo, pa);
        cpa16(sb + 2*TILE_B + soff,   Bhi + gB, true);
        cpa16(sb + 3*TILE_B + soff,   Blo + gB, true);
    }
    asm volatile("cp.async.commit_group;" ::: "memory");
}

template<int MODE>
__global__ void __launch_bounds__(256, 2)
tc_gemm(const __nv_bfloat16* __restrict__ Ahi, const __nv_bfloat16* __restrict__ Alo,
        const __nv_bfloat16* __restrict__ Bhi, const __nv_bfloat16* __restrict__ Blo,
        const float* __restrict__ bias, float* __restrict__ C,
        __nv_bfloat16* __restrict__ Chi, __nv_bfloat16* __restrict__ Clo,
        int M, int N, int K,
        const float* __restrict__ res, const float* __restrict__ scalep)
{
    extern __shared__ char smem[];
    const int tid = threadIdx.x;
    const int bm = blockIdx.y * 128;
    const int bn = blockIdx.x * 128;
    const int warp = tid >> 5;
    const int wm = (warp >> 2) * 64;
    const int wn = (warp & 3) * 32;

    wmma::fragment<wmma::accumulator, 16, 16, 16, float> fc[4][2];
    #pragma unroll
    for (int i = 0; i < 4; i++)
        #pragma unroll
        for (int j = 0; j < 2; j++)
            wmma::fill_fragment(fc[i][j], 0.0f);

    const int nch = K >> 5;
    stage_load(smem, 0, Ahi, Alo, Bhi, Blo, bm, bn, M, K, 0, tid);
    if (nch > 1) stage_load(smem, 1, Ahi, Alo, Bhi, Blo, bm, bn, M, K, 1, tid);

    for (int kc = 0; kc < nch; kc++) {
        if (kc + 1 < nch) asm volatile("cp.async.wait_group 1;" ::: "memory");
        else              asm volatile("cp.async.wait_group 0;" ::: "memory");
        __syncthreads();

        const char* base = smem + (kc & 1) * STAGE_B;
        const __nv_bfloat16* pAh = (const __nv_bfloat16*)(base);
        const __nv_bfloat16* pAl = (const __nv_bfloat16*)(base + TILE_B);
        const __nv_bfloat16* pBh = (const __nv_bfloat16*)(base + 2*TILE_B);
        const __nv_bfloat16* pBl = (const __nv_bfloat16*)(base + 3*TILE_B);

        #pragma unroll
        for (int ks = 0; ks < 32; ks += 16) {
            wmma::fragment<wmma::matrix_b, 16, 16, 16, __nv_bfloat16, wmma::col_major> fbh[2], fbl[2];
            #pragma unroll
            for (int j = 0; j < 2; j++) {
                wmma::load_matrix_sync(fbh[j], pBh + (wn + 16*j)*LDT + ks, LDT);
                wmma::load_matrix_sync(fbl[j], pBl + (wn + 16*j)*LDT + ks, LDT);
            }
            #pragma unroll
            for (int i = 0; i < 4; i++) {
                wmma::fragment<wmma::matrix_a, 16, 16, 16, __nv_bfloat16, wmma::row_major> fah, fal;
                wmma::load_matrix_sync(fah, pAh + (wm + 16*i)*LDT + ks, LDT);
                wmma::load_matrix_sync(fal, pAl + (wm + 16*i)*LDT + ks, LDT);
                #pragma unroll
                for (int j = 0; j < 2; j++) {
                    wmma::mma_sync(fc[i][j], fah, fbh[j], fc[i][j]);
                    wmma::mma_sync(fc[i][j], fah, fbl[j], fc[i][j]);
                    wmma::mma_sync(fc[i][j], fal, fbh[j], fc[i][j]);
                }
            }
        }
        __syncthreads();
        if (kc + 2 < nch)
            stage_load(smem, kc & 1, Ahi, Alo, Bhi, Blo, bm, bn, M, K, kc + 2, tid);
    }

    // ---- epilogue through SMEM ----
    float* Cs = (float*)smem;    // 128 x 132
    #pragma unroll
    for (int i = 0; i < 4; i++)
        #pragma unroll
        for (int j = 0; j < 2; j++)
            wmma::store_matrix_sync(Cs + (wm + 16*i)*132 + wn + 16*j, fc[i][j],
                                    132, wmma::mem_row_major);
    __syncthreads();

    const float scale = (MODE == 1) ? scalep[0] : 1.0f;
    int row = tid >> 1;
    int cbase = (tid & 1) * 64;
    int m = bm + row;
    if (m < M) {
        #pragma unroll
        for (int j = 0; j < 64; j += 4) {
            int n = bn + cbase + j;
            float4 v = *(float4*)(Cs + row*132 + cbase + j);
            float4 bi = *(const float4*)(bias + n);
            v.x += bi.x; v.y += bi.y; v.z += bi.z; v.w += bi.w;
            if (MODE == 2) {
                v.x = gelu_exact(v.x); v.y = gelu_exact(v.y);
                v.z = gelu_exact(v.z); v.w = gelu_exact(v.w);
                uint2 hi, lo;
                cvt_hilo(v, hi, lo);
                *(uint2*)(Chi + (size_t)m*N + n) = hi;
                *(uint2*)(Clo + (size_t)m*N + n) = lo;
            } else {
                if (MODE == 1) {
                    float4 r = *(const float4*)(res + (size_t)m*N + n);
                    v.x = r.x + scale*v.x; v.y = r.y + scale*v.y;
                    v.z = r.z + scale*v.z; v.w = r.w + scale*v.w;
                }
                *(float4*)(C + (size_t)m*N + n) = v;
            }
        }
    }
}

// ---------------- weights + qkv bias -> bf16 hi/lo (one launch) ------------
__global__ void cvt_all(const float* __restrict__ Wq, const float* __restrict__ Wk,
                        const float* __restrict__ Wv, const float* __restrict__ Wo,
                        const float* __restrict__ W1, const float* __restrict__ W2,
                        const float* __restrict__ bq, const float* __restrict__ bk,
                        const float* __restrict__ bv) {
    int i = blockIdx.x * blockDim.x + threadIdx.x;   // src float4 index, 196608 total
    if (i < 196608) {
        const float* src; int soff;
        if      (i < 16384)  { src = Wq; soff = 0; }
        else if (i < 32768)  { src = Wk; soff = 16384; }
        else if (i < 49152)  { src = Wv; soff = 32768; }
        else if (i < 65536)  { src = Wo; soff = 49152; }
        else if (i < 131072) { src = W1; soff = 65536; }
        else                 { src = W2; soff = 131072; }
        int dst = i + ((i >= 49152) ? 16384 : 0);   // skip Wqe slot
        float4 v = ((const float4*)src)[i - soff];
        uint2 h, l;
        cvt_hilo(v, h, l);
        ((uint2*)g_wh)[dst] = h;
        ((uint2*)g_wl)[dst] = l;
    }
    if (i < 768/4) {
        const float* bs = (i < 64) ? bq : ((i < 128) ? bk : bv);
        ((float4*)g_bqkv)[i] = ((const float4*)bs)[i & 63];
    }
}

// -------- Wqe = blockdiag(We^T) @ Wq  (+ bqe = We^T bq) --------------------
// Wqe[o=h*32+c][k] = sum_d We[d][c] * Wq[h*32+d][k]
__global__ void wqe_kernel(const float* __restrict__ Wq, const float* __restrict__ We,
                           const float* __restrict__ bq) {
    int i = blockIdx.x * blockDim.x + threadIdx.x;
    if (i < 65536) {
        int o = i >> 8, k = i & 255;
        int h = o >> 5, c = o & 31;
        float s = 0.f;
        #pragma unroll
        for (int d = 0; d < 32; d++)
            s = fmaf(We[d*EDIM + c], Wq[(h*32 + d)*DD + k], s);
        __nv_bfloat16 hi = __float2bfloat16(s);
        g_wh[WQEO + o*DD + k] = hi;
        g_wl[WQEO + o*DD + k] = __float2bfloat16(s - __bfloat162float(hi));
    } else if (i < 65536 + 256) {
        int o = i - 65536;
        int h = o >> 5, c = o & 31;
        float s = 0.f;
        #pragma unroll
        for (int d = 0; d < 32; d++)
            s = fmaf(We[d*EDIM + c], bq[h*32 + d], s);
        g_bqkv[768 + o] = s;
    }
}

// ---------------- zero init (agg, ssum, smax) ------------------------------
__global__ void zero_kernel() {
    int i = blockIdx.x * blockDim.x + threadIdx.x;
    if (i < NN*DD) g_agg[i] = 0.f;
    if (i < NN*HH) { g_ssum[i] = 0.f; g_smax[i] = 0u; }
}

// ---------------- layernorm -> bf16 hi/lo ----------------------------------
__global__ void ln_kernel(const float* __restrict__ in,
                          const float* __restrict__ g,
                          const float* __restrict__ b,
                          __nv_bfloat16* __restrict__ out_hi,
                          __nv_bfloat16* __restrict__ out_lo) {
    int row = blockIdx.x;
    int t = threadIdx.x;
    float v = in[(size_t)row*DD + t];
    float s = v, s2 = v*v;
    #pragma unroll
    for (int off = 16; off; off >>= 1) {
        s  += __shfl_xor_sync(0xffffffffu, s,  off);
        s2 += __shfl_xor_sync(0xffffffffu, s2, off);
    }
    __shared__ float ws[8], ws2[8], mustd[2];
    int w = t >> 5, lane = t & 31;
    if (lane == 0) { ws[w] = s; ws2[w] = s2; }
    __syncthreads();
    if (t == 0) {
        float ts = 0.f, ts2 = 0.f;
        #pragma unroll
        for (int i = 0; i < 8; i++) { ts += ws[i]; ts2 += ws2[i]; }
        float mu = ts * (1.0f/DD);
        float var = ts2 * (1.0f/DD) - mu*mu;
        mustd[0] = mu;
        mustd[1] = 1.0f / sqrtf(var + 1e-5f);
    }
    __syncthreads();
    float y = (v - mustd[0]) * mustd[1] * g[t] + b[t];
    __nv_bfloat16 h = __float2bfloat16(y);
    out_hi[(size_t)row*DD + t] = h;
    out_lo[(size_t)row*DD + t] = __float2bfloat16(y - __bfloat162float(h));
}

// -------- per-edge scores + segment max: 4 lanes per head ------------------
// score[e,h] = (q.k + qe.ef + q.be) * scale * ew[e]
__global__ __launch_bounds__(256)
void scores_kernel(const int* __restrict__ ei, const float* __restrict__ ew,
                   const float* __restrict__ ef, const float* __restrict__ be) {
    int lane = threadIdx.x & 31;
    size_t e = (size_t)blockIdx.x * 8 + (threadIdx.x >> 5);
    if (e >= NE) return;
    int src = ei[e];
    int dst = ei[NE + e];
    int h = lane >> 2, s = lane & 3;
    const float4* db = (const float4*)(g_qkv + (size_t)dst*DQKV);       // q@0, qe@192
    const float4* k4 = (const float4*)(g_qkv + (size_t)src*DQKV) + 64;  // k
    const float4* e4 = (const float4*)(ef + e*EDIM);
    int qi = h*8 + s*2;
    float4 qa = db[qi],        qb4 = db[qi+1];
    float4 qea = db[192 + qi], qeb = db[192 + qi + 1];
    float4 ka = k4[qi],        kb = k4[qi+1];
    float4 ea = e4[s*2],       eb = e4[s*2+1];
    float4 ba = __ldg((const float4*)be + s*2);
    float4 bb = __ldg((const float4*)be + s*2 + 1);
    float p = dot4(qa, ka) + dot4(qb4, kb)
            + dot4(qea, ea) + dot4(qeb, eb)
            + dot4(qa, ba) + dot4(qb4, bb);
    p += __shfl_xor_sync(0xffffffffu, p, 1);
    p += __shfl_xor_sync(0xffffffffu, p, 2);
    if (s == 0) {
        float w = ew[e] * 0.17677669529663687f;
        float sc = p * w;
        g_scores[e*HH + h] = sc;
        atomicMax(&g_smax[(size_t)dst*HH + h], fenc(sc));
    }
}

// ------- fused: exp(score-max), red ssum, scatter unnormalized e*v ---------
__global__ __launch_bounds__(256)
void expagg_kernel(const int* __restrict__ ei) {
    int lane = threadIdx.x & 31;
    size_t e = (size_t)blockIdx.x * 8 + (threadIdx.x >> 5);
    if (e >= NE) return;
    int src = ei[e];
    int dst = ei[NE + e];
    float ev = 0.f;
    if (lane < HH) {
        float m = fdec(g_smax[(size_t)dst*HH + lane]);
        ev = expf(g_scores[e*HH + lane] - m);
        g_scores[e*HH + lane] = ev;          // keep e for attn-weights pass
        red1(g_ssum + (size_t)dst*HH + lane, ev);
    }
    float w0 = __shfl_sync(0xffffffffu, ev, lane >> 3);
    float w1 = __shfl_sync(0xffffffffu, ev, 4 + (lane >> 3));
    const float4* vr = (const float4*)(g_qkv + (size_t)src*DQKV + 2*DD);  // v
    float* ar = g_agg + (size_t)dst*DD;
    float4 v0 = vr[lane];
    float4 v1 = vr[lane + 32];
    red4(ar + 4*lane,       w0*v0.x, w0*v0.y, w0*v0.z, w0*v0.w);
    red4(ar + 128 + 4*lane, w1*v1.x, w1*v1.y, w1*v1.z, w1*v1.w);
}

// ---------------- attn weights output: e / ssum[dst] -----------------------
__global__ void attnw_kernel(const int* __restrict__ ei, float* __restrict__ attn_out) {
    int e = blockIdx.x * blockDim.x + threadIdx.x;
    if (e >= NE) return;
    int dst = ei[NE + e];
    float4 e0 = *(float4*)(g_scores + (size_t)e*HH);
    float4 e1 = *(float4*)(g_scores + (size_t)e*HH + 4);
    float4 s0 = *(const float4*)(g_ssum + (size_t)dst*HH);
    float4 s1 = *(const float4*)(g_ssum + (size_t)dst*HH + 4);
    e0.x /= s0.x; e0.y /= s0.y; e0.z /= s0.z; e0.w /= s0.w;
    e1.x /= s1.x; e1.y /= s1.y; e1.z /= s1.z; e1.w /= s1.w;
    *(float4*)(attn_out + (size_t)e*HH)     = e0;
    *(float4*)(attn_out + (size_t)e*HH + 4) = e1;
}

// -------- normalize agg by ssum and convert -> bf16 hi/lo ------------------
__global__ void cvt_agg_norm(int n4) {
    int i = blockIdx.x * blockDim.x + threadIdx.x;
    if (i >= n4) return;
    int node = i >> 6;             // 64 float4 per 256-float row
    int j = i & 63;
    int head = j >> 3;
    float s = 1.0f / g_ssum[(size_t)node*HH + head];
    float4 v = ((const float4*)g_agg)[i];
    v.x *= s; v.y *= s; v.z *= s; v.w *= s;
    uint2 h, l;
    cvt_hilo(v, h, l);
    ((uint2*)g_aggh)[i] = h;
    ((uint2*)g_aggl)[i] = l;
}

// ---------------------------------------------------------------------------
extern "C" void kernel_launch(void* const* d_in, const int* in_sizes, int n_in,
                              void* d_out, int out_size) {
    const float* x     = (const float*)d_in[0];
    const int*   ei    = (const int*)  d_in[1];
    const float* ef    = (const float*)d_in[2];
    const float* ew    = (const float*)d_in[3];
    const float* Wq    = (const float*)d_in[4];
    const float* bq    = (const float*)d_in[5];
    const float* Wk    = (const float*)d_in[6];
    const float* bk    = (const float*)d_in[7];
    const float* Wv    = (const float*)d_in[8];
    const float* bv    = (const float*)d_in[9];
    const float* We    = (const float*)d_in[10];
    const float* be    = (const float*)d_in[11];
    const float* Wo    = (const float*)d_in[12];
    const float* bo    = (const float*)d_in[13];
    const float* W1    = (const float*)d_in[14];
    const float* b1    = (const float*)d_in[15];
    const float* W2    = (const float*)d_in[16];
    const float* b2    = (const float*)d_in[17];
    const float* g1    = (const float*)d_in[18];
    const float* be1   = (const float*)d_in[19];
    const float* g2    = (const float*)d_in[20];
    const float* be2   = (const float*)d_in[21];
    const float* alpha = (const float*)d_in[22];
    const float* beta  = (const float*)d_in[23];

    float* out = (float*)d_out;
    float* out_x = out;
    float* out_attn = nullptr;
    if (out_size >= NN*DD + NE*HH) out_attn = out + (size_t)NN*DD;

    float *p_qkv, *p_agg, *p_x1, *p_bqkv;
    __nv_bfloat16 *p_xnh, *p_xnl, *p_aggh, *p_aggl, *p_hh, *p_hl, *p_wh, *p_wl;
    cudaGetSymbolAddress((void**)&p_qkv,  g_qkv);
    cudaGetSymbolAddress((void**)&p_agg,  g_agg);
    cudaGetSymbolAddress((void**)&p_x1,   g_x1);
    cudaGetSymbolAddress((void**)&p_bqkv, g_bqkv);
    cudaGetSymbolAddress((void**)&p_xnh,  g_xnh);
    cudaGetSymbolAddress((void**)&p_xnl,  g_xnl);
    cudaGetSymbolAddress((void**)&p_aggh, g_aggh);
    cudaGetSymbolAddress((void**)&p_aggl, g_aggl);
    cudaGetSymbolAddress((void**)&p_hh,   g_hh);
    cudaGetSymbolAddress((void**)&p_hl,   g_hl);
    cudaGetSymbolAddress((void**)&p_wh,   g_wh);
    cudaGetSymbolAddress((void**)&p_wl,   g_wl);

    cudaFuncSetAttribute(tc_gemm<0>, cudaFuncAttributeMaxDynamicSharedMemorySize, GEMM_SMEM);
    cudaFuncSetAttribute(tc_gemm<1>, cudaFuncAttributeMaxDynamicSharedMemorySize, GEMM_SMEM);
    cudaFuncSetAttribute(tc_gemm<2>, cudaFuncAttributeMaxDynamicSharedMemorySize, GEMM_SMEM);

    const int eblocks = (NE + 7) / 8;
    const int mtiles = (NN + 127) / 128;   // 391

    // 1. zero accumulators
    zero_kernel<<<(NN*DD + 255) / 256, 256>>>();

    // 2. weight/bias conversions
    cvt_all<<<(196608 + 255) / 256, 256>>>(Wq, Wk, Wv, Wo, W1, W2, bq, bk, bv);

    // 3. Wqe = blockdiag(We^T) @ Wq, bqe
    wqe_kernel<<<(65536 + 256 + 255) / 256, 256>>>(Wq, We, bq);

    // 4. LN1 -> bf16 hi/lo
    ln_kernel<<<NN, 256>>>(x, g1, be1, p_xnh, p_xnl);

    // 5. fused q|k|v|qe projection (launch #5 -> ncu profile target)
    dim3 gqkv(DQKV/128, mtiles);
    tc_gemm<0><<<gqkv, 256, GEMM_SMEM>>>(p_xnh, p_xnl, p_wh, p_wl,
                                         p_bqkv, p_qkv, nullptr, nullptr,
                                         NN, DQKV, DD, nullptr, nullptr);

    // 6. scores + segment max (reads ef directly; no edge projection pass)
    scores_kernel<<<eblocks, 256>>>(ei, ew, ef, be);

    // 7. fused exp + ssum + unnormalized scatter-aggregate
    expagg_kernel<<<eblocks, 256>>>(ei);

    // 8. attn weights output
    if (out_attn)
        attnw_kernel<<<(NE + 255) / 256, 256>>>(ei, out_attn);

    // 9. normalize agg + convert to bf16 hi/lo
    cvt_agg_norm<<<(NN*DD/4 + 255) / 256, 256>>>(NN*DD/4);

    // 10. attn out projection + residual
    dim3 g256(DD/128, mtiles);
    tc_gemm<1><<<g256, 256, GEMM_SMEM>>>(p_aggh, p_aggl, p_wh + WOO, p_wl + WOO,
                                         bo, p_x1, nullptr, nullptr, NN, DD, DD, x, alpha);

    // 11. LN2 -> bf16 hi/lo
    ln_kernel<<<NN, 256>>>(p_x1, g2, be2, p_xnh, p_xnl);

    // 12. FFN up + GELU -> bf16 hi/lo h
    dim3 g1024(D4/128, mtiles);
    tc_gemm<2><<<g1024, 256, GEMM_SMEM>>>(p_xnh, p_xnl, p_wh + W1O, p_wl + W1O,
                                          b1, nullptr, p_hh, p_hl, NN, D4, DD, nullptr, nullptr);

    // 13. FFN down + residual -> final x into d_out
    tc_gemm<1><<<g256, 256, GEMM_SMEM>>>(p_hh, p_hl, p_wh + W2O, p_wl + W2O,
                                         b2, out_x, nullptr, nullptr, NN, DD, D4, p_x1, beta);
}